// round 7
// baseline (speedup 1.0000x reference)
#include <cuda_runtime.h>
#include <math.h>

#define B_    4
#define HW_   512
#define PLANE_ 262144
#define NBIN_ 4913
#define NPIXD 1048576.0

__device__ __align__(128) unsigned char  g_kmode[12 * PLANE_];
__device__ __align__(128) unsigned short g_bin[4 * PLANE_];
__device__ unsigned int g_hist[NBIN_];              // zero-init; re-zeroed in params_kernel
__device__ __align__(128) float g_htab[NBIN_ * 32]; // pre-BN2 "tt"
__device__ float g_d1[4 * 32 * 171 * 171];
__device__ float g_d2[4 * 32 * 57 * 57];
__device__ float g_d3[4 * 32 * 19 * 19];
__device__ float g_d4[4 * 32 * 7 * 7];
__device__ float g_d5[4 * 32 * 3 * 3];
__device__ float g_d6[4 * 32];
__device__ float g_scale2[32], g_bias2[32];
__device__ double g_lvS[192], g_lvQ[192];           // per-level (6x32) weighted stats
__device__ float g_cA[384], g_cB[384];

__device__ __forceinline__ float leaky(float v) { return fmaxf(v, 0.01f * v); }

template <int H>
__device__ __forceinline__ int upcnt(int i) {
    return (512 * (i + 1) + H - 1) / H - (512 * i + H - 1) / H;
}

// ---------------- 1: mode pooling ------------------------------------------
#define MROWS 8
__global__ __launch_bounds__(128) void mode_kernel(const float* __restrict__ x) {
    __shared__ unsigned int hist[138 * 5];
    const int bc = blockIdx.z, cs = blockIdx.y;
    const int y0 = blockIdx.x * MROWS;
    const int t  = threadIdx.x;
    const int colbase = cs * 128 - 5;
    const float* img = x + bc * PLANE_;

    for (int i = t; i < 138 * 5; i += 128) hist[i] = 0;
    __syncthreads();

    auto addrow = [&](int sy, int sign) {
        int r = sy; if (r < 0) r = -r; else if (r >= HW_) r = 1022 - r;
        const float* row = img + r * HW_;
        for (int xp = t; xp < 138; xp += 128) {
            int sc = colbase + xp;
            int sx = sc < 0 ? -sc : (sc >= HW_ ? 1022 - sc : sc);
            int q = __float2int_rn(row[sx] * 15.9375f);
            q = q < 0 ? 0 : (q > 16 ? 16 : q);
            unsigned int inc = 1u << ((q & 3) * 8);
            int addr = xp * 5 + (q >> 2);
            if (sign > 0) hist[addr] += inc; else hist[addr] -= inc;
        }
    };

    for (int sy = y0 - 5; sy < y0 + 5; ++sy) addrow(sy, +1);

    for (int y = y0; y < y0 + MROWS; ++y) {
        addrow(y + 5, +1);
        __syncthreads();
        {
            unsigned int s0 = 0, s1 = 0, s2 = 0, s3 = 0, s4 = 0;
            #pragma unroll
            for (int k = 0; k < 11; ++k) {
                const unsigned int* h = &hist[(t + k) * 5];
                s0 += h[0]; s1 += h[1]; s2 += h[2]; s3 += h[3]; s4 += h[4];
            }
            unsigned int best = s0 & 255u; int bl = 0;
            #define UPD(cnt, l) { unsigned int c_ = (cnt); if (c_ > best) { best = c_; bl = (l); } }
            UPD((s0 >> 8) & 255u, 1)  UPD((s0 >> 16) & 255u, 2)  UPD(s0 >> 24, 3)
            UPD(s1 & 255u, 4) UPD((s1 >> 8) & 255u, 5) UPD((s1 >> 16) & 255u, 6) UPD(s1 >> 24, 7)
            UPD(s2 & 255u, 8) UPD((s2 >> 8) & 255u, 9) UPD((s2 >> 16) & 255u, 10) UPD(s2 >> 24, 11)
            UPD(s3 & 255u, 12) UPD((s3 >> 8) & 255u, 13) UPD((s3 >> 16) & 255u, 14) UPD(s3 >> 24, 15)
            UPD(s4 & 255u, 16)
            #undef UPD
            g_kmode[bc * PLANE_ + y * HW_ + cs * 128 + t] = (unsigned char)bl;
        }
        __syncthreads();
        addrow(y - 5, -1);
    }
}

// ---------------- 2: joint-bin plane + 17^3 histogram -----------------------
__global__ __launch_bounds__(256) void bin_kernel() {
    __shared__ unsigned int sh[NBIN_];
    int t = threadIdx.x;
    for (int i = t; i < NBIN_; i += 256) sh[i] = 0;
    __syncthreads();
    int base = blockIdx.x * 4096;
    #pragma unroll 4
    for (int i = 0; i < 16; ++i) {
        int gp = base + i * 256 + t;
        int b = gp >> 18, off = gp & (PLANE_ - 1);
        const unsigned char* p = g_kmode + b * 3 * PLANE_ + off;
        int bin = p[0] + 17 * p[PLANE_] + 289 * p[2 * PLANE_];
        g_bin[gp] = (unsigned short)bin;
        atomicAdd(&sh[bin], 1u);
    }
    __syncthreads();
    for (int i = t; i < NBIN_; i += 256) {
        unsigned int v = sh[i];
        if (v) atomicAdd(&g_hist[i], v);
    }
}

// ---------------- 3: BN1 + BN2 params + htab, one block ---------------------
__global__ __launch_bounds__(1024) void params_kernel(
        const float* __restrict__ w1, const float* __restrict__ b1,
        const float* __restrict__ w2, const float* __restrict__ b2,
        const float* __restrict__ g1, const float* __restrict__ be1,
        const float* __restrict__ w3, const float* __restrict__ b3,
        const float* __restrict__ g2, const float* __restrict__ be2) {
    __shared__ float sw1[18], sb1[6], ss1[32], st1[32];
    __shared__ double rs[32][33], rq[32][33];
    int t = threadIdx.x;
    if (t < 18) sw1[t] = w1[t];
    if (t < 6)  sb1[t] = b1[t];
    __syncthreads();

    int c = t & 31, g = t >> 5;
    float w2c[6];
    #pragma unroll
    for (int o = 0; o < 6; ++o) w2c[o] = w2[c * 6 + o];
    float bc2 = b2[c];

    // pass A: BN1 stats
    double s = 0.0, q = 0.0;
    for (int bin = g; bin < NBIN_; bin += 32) {
        unsigned int cnt = g_hist[bin];
        if (!cnt) continue;
        int k2 = bin / 289, rm = bin - 289 * k2, k1 = rm / 17, k0 = rm - 17 * k1;
        float x0 = k0 * 0.0625f, x1 = k1 * 0.0625f, x2 = k2 * 0.0625f;
        float v = bc2;
        #pragma unroll
        for (int o = 0; o < 6; ++o) {
            float m = fmaf(sw1[o*3+2], x2, fmaf(sw1[o*3+1], x1, fmaf(sw1[o*3], x0, sb1[o])));
            v = fmaf(w2c[o], leaky(m), v);
        }
        double cf = (double)cnt;
        s += cf * v; q += cf * ((double)v * v);
    }
    rs[g][c] = s; rq[g][c] = q;
    __syncthreads();
    if (t < 32) {
        double S = 0.0, Q = 0.0;
        for (int j = 0; j < 32; ++j) { S += rs[j][t]; Q += rq[j][t]; }
        double mean = S / NPIXD, var = Q / NPIXD - mean * mean;
        float sc = g1[t] * (float)(1.0 / sqrt(var + 1e-5));
        ss1[t] = sc; st1[t] = be1[t] - (float)mean * sc;
    }
    __syncthreads();

    // pass B: chained BN2 stats + htab store (pre-BN2 tt)
    float s1 = ss1[c], t1 = st1[c], w3c = w3[c], b3c = b3[c];
    s = 0.0; q = 0.0;
    for (int bin = g; bin < NBIN_; bin += 32) {
        int k2 = bin / 289, rm = bin - 289 * k2, k1 = rm / 17, k0 = rm - 17 * k1;
        float x0 = k0 * 0.0625f, x1 = k1 * 0.0625f, x2 = k2 * 0.0625f;
        float v = bc2;
        #pragma unroll
        for (int o = 0; o < 6; ++o) {
            float m = fmaf(sw1[o*3+2], x2, fmaf(sw1[o*3+1], x1, fmaf(sw1[o*3], x0, sb1[o])));
            v = fmaf(w2c[o], leaky(m), v);
        }
        float u  = leaky(fmaf(v, s1, t1));
        float tt = fmaf(u, w3c, b3c);
        g_htab[bin * 32 + c] = tt;
        double cf = (double)g_hist[bin];
        s += cf * tt; q += cf * ((double)tt * tt);
    }
    __syncthreads();
    rs[g][c] = s; rq[g][c] = q;
    __syncthreads();
    if (t < 32) {
        double S = 0.0, Q = 0.0;
        for (int j = 0; j < 32; ++j) { S += rs[j][t]; Q += rq[j][t]; }
        double mean = S / NPIXD, var = Q / NPIXD - mean * mean;
        float sc = g2[t] * (float)(1.0 / sqrt(var + 1e-5));
        g_scale2[t] = sc; g_bias2[t] = be2[t] - (float)mean * sc;
    }
    // cleanup for graph replay + zero level accumulators (all 6 levels)
    for (int i = t; i < NBIN_; i += 1024) g_hist[i] = 0u;
    if (t < 192) { g_lvS[t] = 0.0; g_lvQ[t] = 0.0; }
}

// ---------------- 4: level-1 downsample + fused level-0 stats (double) ------
__global__ __launch_bounds__(256) void down1_kernel(const float* __restrict__ kd) {
    __shared__ float skd[288];
    __shared__ double sdS[32], sdQ[32];
    int t = threadIdx.x;
    for (int i = t; i < 288; i += 256) skd[i] = kd[i];
    if (t < 32) { sdS[t] = 0.0; sdQ[t] = 0.0; }
    __syncthreads();

    int gid = blockIdx.x * 256 + t;
    const int TOT = B_ * 171 * 171 * 4;
    bool valid = gid < TOT;
    int gg = valid ? gid : 0;
    int cg = gg & 3; int rest = gg >> 2;
    int xo = rest % 171; int r2 = rest / 171;
    int yo = r2 % 171;   int b  = r2 / 171;
    int c0 = cg * 8;

    float s2[8], t2[8];
    #pragma unroll
    for (int j = 0; j < 8; ++j) { s2[j] = g_scale2[c0 + j]; t2[j] = g_bias2[c0 + j]; }

    float acc[8] = {0.f,0.f,0.f,0.f,0.f,0.f,0.f,0.f};
    if (valid) {
        const unsigned short* binp = g_bin + b * PLANE_;
        #pragma unroll
        for (int r = 0; r < 3; ++r) {
            int iy = 3 * yo - 1 + r;
            if (iy < 0 || iy >= HW_) continue;
            #pragma unroll
            for (int sx = 0; sx < 3; ++sx) {
                int ix = 3 * xo - 1 + sx;
                if (ix < 0 || ix >= HW_) continue;
                int bin = binp[iy * HW_ + ix];
                const float4* hrow = (const float4*)(g_htab + bin * 32 + c0);
                float4 v0 = hrow[0], v1 = hrow[1];
                float hv[8] = {v0.x,v0.y,v0.z,v0.w,v1.x,v1.y,v1.z,v1.w};
                int kb = r * 3 + sx;
                #pragma unroll
                for (int j = 0; j < 8; ++j) {
                    float h = leaky(fmaf(hv[j], s2[j], t2[j]));
                    acc[j] = fmaf(skd[(c0 + j) * 9 + kb], h, acc[j]);
                }
            }
        }
        float* outp = g_d1 + ((b * 32 + c0) * 171 + yo) * 171 + xo;
        #pragma unroll
        for (int j = 0; j < 8; ++j) outp[j * 29241] = acc[j];
    }
    // level-0 weighted stats in FULL double (variance cancellation safety)
    double w = valid ? (double)(upcnt<171>(yo) * upcnt<171>(xo)) : 0.0;
    double pS[8], pQ[8];
    #pragma unroll
    for (int j = 0; j < 8; ++j) {
        double a = (double)acc[j];
        pS[j] = w * a; pQ[j] = w * a * a;
    }
    #pragma unroll
    for (int off = 4; off < 32; off <<= 1)
        #pragma unroll
        for (int j = 0; j < 8; ++j) {
            pS[j] += __shfl_xor_sync(0xFFFFFFFFu, pS[j], off);
            pQ[j] += __shfl_xor_sync(0xFFFFFFFFu, pQ[j], off);
        }
    int lane = t & 31;
    if (lane < 4) {
        int cc = lane * 8;
        #pragma unroll
        for (int j = 0; j < 8; ++j) {
            atomicAdd(&sdS[cc + j], pS[j]);
            atomicAdd(&sdQ[cc + j], pQ[j]);
        }
    }
    __syncthreads();
    if (t < 32) {
        if (sdS[t] != 0.0) atomicAdd(&g_lvS[t], sdS[t]);
        if (sdQ[t] != 0.0) atomicAdd(&g_lvQ[t], sdQ[t]);
    }
}

// ---------------- 5: full per-plane pyramid d1->d2..d6 + stats lvl1..5 ------
template <int HIN, int HOUT>
__device__ __forceinline__ void pyr_step(const float* __restrict__ in,
                                         float* sh_out, float* __restrict__ g_out,
                                         const float* k, int t,
                                         double& aS, double& aQ) {
    const int N = HOUT * HOUT;
    for (int idx = t; idx < N; idx += 256) {
        int yo = idx / HOUT, xo = idx - yo * HOUT;
        float acc = 0.f;
        #pragma unroll
        for (int r = 0; r < 3; ++r) {
            int iy = 3 * yo - 1 + r;
            if (iy < 0 || iy >= HIN) continue;
            #pragma unroll
            for (int sx = 0; sx < 3; ++sx) {
                int ix = 3 * xo - 1 + sx;
                if (ix < 0 || ix >= HIN) continue;
                acc = fmaf(k[r * 3 + sx], in[iy * HIN + ix], acc);
            }
        }
        if (sh_out) sh_out[idx] = acc;
        g_out[idx] = acc;
        double w = (double)(upcnt<HOUT>(yo) * upcnt<HOUT>(xo));
        double a = (double)acc;
        aS += w * a; aQ += w * a * a;
    }
}

__global__ __launch_bounds__(256) void pyr_kernel(const float* __restrict__ kd) {
    __shared__ float s2[57 * 57];
    __shared__ float s3[19 * 19];
    __shared__ float s4[49];
    __shared__ float s5[9];
    __shared__ double wS[8][5], wQ[8][5];
    int t = threadIdx.x;
    int blk = blockIdx.x;            // b*32 + c
    int c = blk & 31;
    float k[9];
    #pragma unroll
    for (int j = 0; j < 9; ++j) k[j] = kd[c * 9 + j];

    double aS[5] = {0,0,0,0,0}, aQ[5] = {0,0,0,0,0};

    pyr_step<171, 57>(g_d1 + blk * 29241, s2, g_d2 + blk * 3249, k, t, aS[0], aQ[0]);
    __syncthreads();
    pyr_step<57, 19>(s2, s3, g_d3 + blk * 361, k, t, aS[1], aQ[1]);
    __syncthreads();
    pyr_step<19, 7>(s3, s4, g_d4 + blk * 49, k, t, aS[2], aQ[2]);
    __syncthreads();
    pyr_step<7, 3>(s4, s5, g_d5 + blk * 9, k, t, aS[3], aQ[3]);
    __syncthreads();
    pyr_step<3, 1>(s5, (float*)0, g_d6 + blk, k, t, aS[4], aQ[4]);

    // block-reduce 5 stat pairs (double)
    int lane = t & 31, wid = t >> 5;
    #pragma unroll
    for (int l = 0; l < 5; ++l)
        #pragma unroll
        for (int r = 16; r; r >>= 1) {
            aS[l] += __shfl_down_sync(0xFFFFFFFFu, aS[l], r);
            aQ[l] += __shfl_down_sync(0xFFFFFFFFu, aQ[l], r);
        }
    if (lane == 0)
        #pragma unroll
        for (int l = 0; l < 5; ++l) { wS[wid][l] = aS[l]; wQ[wid][l] = aQ[l]; }
    __syncthreads();
    if (t < 5) {
        double S = 0.0, Q = 0.0;
        #pragma unroll
        for (int j = 0; j < 8; ++j) { S += wS[j][t]; Q += wQ[j][t]; }
        atomicAdd(&g_lvS[(t + 1) * 32 + c], S);
        atomicAdd(&g_lvQ[(t + 1) * 32 + c], Q);
    }
}

// ---------------- 6: branch coefficient finalize ----------------------------
__global__ void coef_kernel(
        const float* __restrict__ kw, const float* __restrict__ gw, const float* __restrict__ bw,
        const float* __restrict__ kh, const float* __restrict__ gh, const float* __restrict__ bh) {
    int t = threadIdx.x;
    if (t < 192) {
        int l = t >> 5, c = t & 31;
        double mean = g_lvS[t] / NPIXD;
        double var  = g_lvQ[t] / NPIXD - mean * mean;
        double k = (double)kw[c];
        double inv = 1.0 / sqrt(k * k * var + 1e-5);
        g_cA[l * 64 + c] = (float)(k * gw[c] * inv);
        g_cB[l * 64 + c] = (float)(bw[c] - k * mean * gw[c] * inv);
        k = (double)kh[c];
        inv = 1.0 / sqrt(k * k * var + 1e-5);
        g_cA[l * 64 + 32 + c] = (float)(k * gh[c] * inv);
        g_cB[l * 64 + 32 + c] = (float)(bh[c] - k * mean * gh[c] * inv);
    }
}

// ---------------- 7: final gather + sum over 6 levels (4 px/thread) ---------
__global__ __launch_bounds__(256) void final_kernel(float* __restrict__ out) {
    __shared__ float sA[384], sB[384];
    for (int i = threadIdx.x; i < 384; i += 256) { sA[i] = g_cA[i]; sB[i] = g_cB[i]; }
    __syncthreads();

    int idx = blockIdx.x * 256 + threadIdx.x;
    int x4 = (idx & 127) << 2;
    int y  = (idx >> 7) & 511;
    int ch = (idx >> 16) & 31;
    int b  = idx >> 21;
    float aw[4] = {0.f,0.f,0.f,0.f};
    float ah[4] = {0.f,0.f,0.f,0.f};

    #define LVL(L, HH, PTR) { \
        int ri = (y * HH) >> 9; \
        const float* rowp = PTR + ((b * 32 + ch) * HH + ri) * HH; \
        float A0 = sA[(L)*64+ch], B0 = sB[(L)*64+ch]; \
        float A1 = sA[(L)*64+32+ch], B1 = sB[(L)*64+32+ch]; \
        _Pragma("unroll") \
        for (int p = 0; p < 4; ++p) { \
            int ci = ((x4 + p) * HH) >> 9; \
            float dv = rowp[ci]; \
            float tw = fmaf(dv, A0, B0); aw[p] += fmaxf(tw, 0.01f * tw); \
            float th = fmaf(dv, A1, B1); ah[p] += fmaxf(th, 0.01f * th); } }

    LVL(0, 171, g_d1)
    LVL(1, 57,  g_d2)
    LVL(2, 19,  g_d3)
    LVL(3, 7,   g_d4)
    LVL(4, 3,   g_d5)
    LVL(5, 1,   g_d6)
    #undef LVL

    int ob = ((b * 64 + ch) << 18) + (y << 9) + x4;
    *(float4*)(out + ob) = make_float4(aw[0], aw[1], aw[2], aw[3]);
    *(float4*)(out + ob + (32 << 18)) = make_float4(ah[0], ah[1], ah[2], ah[3]);
}

// ---------------- launch ----------------------------------------------------
extern "C" void kernel_launch(void* const* d_in, const int* in_sizes, int n_in,
                              void* d_out, int out_size) {
    const float* x    = (const float*)d_in[0];
    const float* w1   = (const float*)d_in[1];
    const float* b1   = (const float*)d_in[2];
    const float* w2   = (const float*)d_in[3];
    const float* b2   = (const float*)d_in[4];
    const float* bn1g = (const float*)d_in[5];
    const float* bn1b = (const float*)d_in[6];
    const float* w3   = (const float*)d_in[7];
    const float* b3   = (const float*)d_in[8];
    const float* bn2g = (const float*)d_in[9];
    const float* bn2b = (const float*)d_in[10];
    const float* kd   = (const float*)d_in[11];
    const float* kw   = (const float*)d_in[12];
    const float* bwg  = (const float*)d_in[13];
    const float* bwb  = (const float*)d_in[14];
    const float* kh   = (const float*)d_in[15];
    const float* bhg  = (const float*)d_in[16];
    const float* bhb  = (const float*)d_in[17];
    float* out = (float*)d_out;

    mode_kernel<<<dim3(64, 4, 12), 128>>>(x);
    bin_kernel<<<256, 256>>>();
    params_kernel<<<1, 1024>>>(w1, b1, w2, b2, bn1g, bn1b, w3, b3, bn2g, bn2b);
    down1_kernel<<<(B_ * 171 * 171 * 4 + 255) / 256, 256>>>(kd);
    pyr_kernel<<<128, 256>>>(kd);
    coef_kernel<<<1, 192>>>(kw, bwg, bwb, kh, bhg, bhb);
    final_kernel<<<32768, 256>>>(out);
}

// round 9
// speedup vs baseline: 1.0590x; 1.0590x over previous
#include <cuda_runtime.h>
#include <math.h>

#define B_    4
#define HW_   512
#define PLANE_ 262144
#define NBIN_ 4913
#define NPIXD 1048576.0

__device__ __align__(128) unsigned char  g_kmode[12 * PLANE_];
__device__ __align__(128) unsigned short g_bin[4 * PLANE_];
__device__ unsigned int g_hist[NBIN_];              // zero-init; re-zeroed in params_kernel
__device__ __align__(128) float g_htab[NBIN_ * 32]; // pre-BN2 "tt"
__device__ float g_d1[4 * 32 * 171 * 171];
__device__ float g_d2[4 * 32 * 57 * 57];
__device__ float g_d3[4 * 32 * 19 * 19];
__device__ float g_d4[4 * 32 * 7 * 7];
__device__ float g_d5[4 * 32 * 3 * 3];
__device__ float g_d6[4 * 32];
__device__ float g_scale2[32], g_bias2[32];
__device__ double g_lvS[192], g_lvQ[192];           // per-level (6x32) weighted stats
__device__ float g_cA[384], g_cB[384];

__device__ __forceinline__ float leaky(float v) { return fmaxf(v, 0.01f * v); }

template <int H>
__device__ __forceinline__ int upcnt(int i) {
    return (512 * (i + 1) + H - 1) / H - (512 * i + H - 1) / H;
}

// ---------------- 1: mode pooling ------------------------------------------
#define MROWS 8
__global__ __launch_bounds__(128) void mode_kernel(const float* __restrict__ x) {
    __shared__ unsigned int hist[138 * 5];
    const int bc = blockIdx.z, cs = blockIdx.y;
    const int y0 = blockIdx.x * MROWS;
    const int t  = threadIdx.x;
    const int colbase = cs * 128 - 5;
    const float* img = x + bc * PLANE_;

    for (int i = t; i < 138 * 5; i += 128) hist[i] = 0;
    __syncthreads();

    auto addrow = [&](int sy, int sign) {
        int r = sy; if (r < 0) r = -r; else if (r >= HW_) r = 1022 - r;
        const float* row = img + r * HW_;
        for (int xp = t; xp < 138; xp += 128) {
            int sc = colbase + xp;
            int sx = sc < 0 ? -sc : (sc >= HW_ ? 1022 - sc : sc);
            int q = __float2int_rn(row[sx] * 15.9375f);
            q = q < 0 ? 0 : (q > 16 ? 16 : q);
            unsigned int inc = 1u << ((q & 3) * 8);
            int addr = xp * 5 + (q >> 2);
            if (sign > 0) hist[addr] += inc; else hist[addr] -= inc;
        }
    };

    for (int sy = y0 - 5; sy < y0 + 5; ++sy) addrow(sy, +1);

    for (int y = y0; y < y0 + MROWS; ++y) {
        addrow(y + 5, +1);
        __syncthreads();
        {
            unsigned int s0 = 0, s1 = 0, s2 = 0, s3 = 0, s4 = 0;
            #pragma unroll
            for (int k = 0; k < 11; ++k) {
                const unsigned int* h = &hist[(t + k) * 5];
                s0 += h[0]; s1 += h[1]; s2 += h[2]; s3 += h[3]; s4 += h[4];
            }
            unsigned int best = s0 & 255u; int bl = 0;
            #define UPD(cnt, l) { unsigned int c_ = (cnt); if (c_ > best) { best = c_; bl = (l); } }
            UPD((s0 >> 8) & 255u, 1)  UPD((s0 >> 16) & 255u, 2)  UPD(s0 >> 24, 3)
            UPD(s1 & 255u, 4) UPD((s1 >> 8) & 255u, 5) UPD((s1 >> 16) & 255u, 6) UPD(s1 >> 24, 7)
            UPD(s2 & 255u, 8) UPD((s2 >> 8) & 255u, 9) UPD((s2 >> 16) & 255u, 10) UPD(s2 >> 24, 11)
            UPD(s3 & 255u, 12) UPD((s3 >> 8) & 255u, 13) UPD((s3 >> 16) & 255u, 14) UPD(s3 >> 24, 15)
            UPD(s4 & 255u, 16)
            #undef UPD
            g_kmode[bc * PLANE_ + y * HW_ + cs * 128 + t] = (unsigned char)bl;
        }
        __syncthreads();
        addrow(y - 5, -1);
    }
}

// ---------------- 2: joint-bin plane + 17^3 histogram -----------------------
__global__ __launch_bounds__(256) void bin_kernel() {
    __shared__ unsigned int sh[NBIN_];
    int t = threadIdx.x;
    for (int i = t; i < NBIN_; i += 256) sh[i] = 0;
    __syncthreads();
    int base = blockIdx.x * 4096;
    #pragma unroll 4
    for (int i = 0; i < 16; ++i) {
        int gp = base + i * 256 + t;
        int b = gp >> 18, off = gp & (PLANE_ - 1);
        const unsigned char* p = g_kmode + b * 3 * PLANE_ + off;
        int bin = p[0] + 17 * p[PLANE_] + 289 * p[2 * PLANE_];
        g_bin[gp] = (unsigned short)bin;
        atomicAdd(&sh[bin], 1u);
    }
    __syncthreads();
    for (int i = t; i < NBIN_; i += 256) {
        unsigned int v = sh[i];
        if (v) atomicAdd(&g_hist[i], v);
    }
}

// ---------------- 3: BN1 + BN2 params + htab, one block ---------------------
__global__ __launch_bounds__(1024) void params_kernel(
        const float* __restrict__ w1, const float* __restrict__ b1,
        const float* __restrict__ w2, const float* __restrict__ b2,
        const float* __restrict__ g1, const float* __restrict__ be1,
        const float* __restrict__ w3, const float* __restrict__ b3,
        const float* __restrict__ g2, const float* __restrict__ be2) {
    __shared__ float sw1[18], sb1[6], ss1[32], st1[32];
    __shared__ double rs[32][33], rq[32][33];
    int t = threadIdx.x;
    if (t < 18) sw1[t] = w1[t];
    if (t < 6)  sb1[t] = b1[t];
    __syncthreads();

    int c = t & 31, g = t >> 5;
    float w2c[6];
    #pragma unroll
    for (int o = 0; o < 6; ++o) w2c[o] = w2[c * 6 + o];
    float bc2 = b2[c];

    // pass A: BN1 stats
    double s = 0.0, q = 0.0;
    for (int bin = g; bin < NBIN_; bin += 32) {
        unsigned int cnt = g_hist[bin];
        if (!cnt) continue;
        int k2 = bin / 289, rm = bin - 289 * k2, k1 = rm / 17, k0 = rm - 17 * k1;
        float x0 = k0 * 0.0625f, x1 = k1 * 0.0625f, x2 = k2 * 0.0625f;
        float v = bc2;
        #pragma unroll
        for (int o = 0; o < 6; ++o) {
            float m = fmaf(sw1[o*3+2], x2, fmaf(sw1[o*3+1], x1, fmaf(sw1[o*3], x0, sb1[o])));
            v = fmaf(w2c[o], leaky(m), v);
        }
        double cf = (double)cnt;
        s += cf * v; q += cf * ((double)v * v);
    }
    rs[g][c] = s; rq[g][c] = q;
    __syncthreads();
    if (t < 32) {
        double S = 0.0, Q = 0.0;
        for (int j = 0; j < 32; ++j) { S += rs[j][t]; Q += rq[j][t]; }
        double mean = S / NPIXD, var = Q / NPIXD - mean * mean;
        float sc = g1[t] * (float)(1.0 / sqrt(var + 1e-5));
        ss1[t] = sc; st1[t] = be1[t] - (float)mean * sc;
    }
    __syncthreads();

    // pass B: chained BN2 stats + htab store (pre-BN2 tt)
    float s1 = ss1[c], t1 = st1[c], w3c = w3[c], b3c = b3[c];
    s = 0.0; q = 0.0;
    for (int bin = g; bin < NBIN_; bin += 32) {
        int k2 = bin / 289, rm = bin - 289 * k2, k1 = rm / 17, k0 = rm - 17 * k1;
        float x0 = k0 * 0.0625f, x1 = k1 * 0.0625f, x2 = k2 * 0.0625f;
        float v = bc2;
        #pragma unroll
        for (int o = 0; o < 6; ++o) {
            float m = fmaf(sw1[o*3+2], x2, fmaf(sw1[o*3+1], x1, fmaf(sw1[o*3], x0, sb1[o])));
            v = fmaf(w2c[o], leaky(m), v);
        }
        float u  = leaky(fmaf(v, s1, t1));
        float tt = fmaf(u, w3c, b3c);
        g_htab[bin * 32 + c] = tt;
        double cf = (double)g_hist[bin];
        s += cf * tt; q += cf * ((double)tt * tt);
    }
    __syncthreads();
    rs[g][c] = s; rq[g][c] = q;
    __syncthreads();
    if (t < 32) {
        double S = 0.0, Q = 0.0;
        for (int j = 0; j < 32; ++j) { S += rs[j][t]; Q += rq[j][t]; }
        double mean = S / NPIXD, var = Q / NPIXD - mean * mean;
        float sc = g2[t] * (float)(1.0 / sqrt(var + 1e-5));
        g_scale2[t] = sc; g_bias2[t] = be2[t] - (float)mean * sc;
    }
    // cleanup for graph replay + zero level accumulators (all 6 levels)
    for (int i = t; i < NBIN_; i += 1024) g_hist[i] = 0u;
    if (t < 192) { g_lvS[t] = 0.0; g_lvQ[t] = 0.0; }
}

// ---------------- 4: level-1 downsample (pure compute, no stats) ------------
__global__ __launch_bounds__(256) void down1_kernel(const float* __restrict__ kd) {
    __shared__ float skd[288];
    int t = threadIdx.x;
    for (int i = t; i < 288; i += 256) skd[i] = kd[i];
    __syncthreads();

    int gid = blockIdx.x * 256 + t;
    const int TOT = B_ * 171 * 171 * 4;
    if (gid >= TOT) return;
    int cg = gid & 3; int rest = gid >> 2;
    int xo = rest % 171; int r2 = rest / 171;
    int yo = r2 % 171;   int b  = r2 / 171;
    int c0 = cg * 8;

    float s2[8], t2[8];
    #pragma unroll
    for (int j = 0; j < 8; ++j) { s2[j] = g_scale2[c0 + j]; t2[j] = g_bias2[c0 + j]; }

    const unsigned short* binp = g_bin + b * PLANE_;
    float acc[8] = {0.f,0.f,0.f,0.f,0.f,0.f,0.f,0.f};
    #pragma unroll
    for (int r = 0; r < 3; ++r) {
        int iy = 3 * yo - 1 + r;
        if (iy < 0 || iy >= HW_) continue;
        #pragma unroll
        for (int sx = 0; sx < 3; ++sx) {
            int ix = 3 * xo - 1 + sx;
            if (ix < 0 || ix >= HW_) continue;
            int bin = binp[iy * HW_ + ix];
            const float4* hrow = (const float4*)(g_htab + bin * 32 + c0);
            float4 v0 = hrow[0], v1 = hrow[1];
            float hv[8] = {v0.x,v0.y,v0.z,v0.w,v1.x,v1.y,v1.z,v1.w};
            int kb = r * 3 + sx;
            #pragma unroll
            for (int j = 0; j < 8; ++j) {
                float h = leaky(fmaf(hv[j], s2[j], t2[j]));
                acc[j] = fmaf(skd[(c0 + j) * 9 + kb], h, acc[j]);
            }
        }
    }
    float* outp = g_d1 + ((b * 32 + c0) * 171 + yo) * 171 + xo;
    #pragma unroll
    for (int j = 0; j < 8; ++j) outp[j * 29241] = acc[j];
}

// ---------------- 5: per-plane pyramid d1->d2..d6 + stats lvl0..5 -----------
template <int HIN, int HOUT>
__device__ __forceinline__ void pyr_step(const float* __restrict__ in,
                                         float* sh_out, float* __restrict__ g_out,
                                         const float* k, int t,
                                         double& aS, double& aQ) {
    const int N = HOUT * HOUT;
    for (int idx = t; idx < N; idx += 256) {
        int yo = idx / HOUT, xo = idx - yo * HOUT;
        float acc = 0.f;
        #pragma unroll
        for (int r = 0; r < 3; ++r) {
            int iy = 3 * yo - 1 + r;
            if (iy < 0 || iy >= HIN) continue;
            #pragma unroll
            for (int sx = 0; sx < 3; ++sx) {
                int ix = 3 * xo - 1 + sx;
                if (ix < 0 || ix >= HIN) continue;
                acc = fmaf(k[r * 3 + sx], in[iy * HIN + ix], acc);
            }
        }
        if (sh_out) sh_out[idx] = acc;
        g_out[idx] = acc;
        double w = (double)(upcnt<HOUT>(yo) * upcnt<HOUT>(xo));
        double a = (double)acc;
        aS += w * a; aQ += w * a * a;
    }
}

__global__ __launch_bounds__(256) void pyr_kernel(const float* __restrict__ kd) {
    __shared__ float s2[57 * 57];
    __shared__ float s3[19 * 19];
    __shared__ float s4[49];
    __shared__ float s5[9];
    __shared__ double wS[8][6], wQ[8][6];
    int t = threadIdx.x;
    int blk = blockIdx.x;            // b*32 + c
    int c = blk & 31;
    float k[9];
    #pragma unroll
    for (int j = 0; j < 9; ++j) k[j] = kd[c * 9 + j];

    double aS[6] = {0,0,0,0,0,0}, aQ[6] = {0,0,0,0,0,0};

    // level-0 stats over the d1 plane (hot in L2; 2 doubles/thread only)
    {
        const float* d1p = g_d1 + blk * 29241;
        for (int idx = t; idx < 29241; idx += 256) {
            int yo = idx / 171, xo = idx - yo * 171;
            double w = (double)(upcnt<171>(yo) * upcnt<171>(xo));
            double a = (double)d1p[idx];
            aS[0] += w * a; aQ[0] += w * a * a;
        }
    }

    pyr_step<171, 57>(g_d1 + blk * 29241, s2, g_d2 + blk * 3249, k, t, aS[1], aQ[1]);
    __syncthreads();
    pyr_step<57, 19>(s2, s3, g_d3 + blk * 361, k, t, aS[2], aQ[2]);
    __syncthreads();
    pyr_step<19, 7>(s3, s4, g_d4 + blk * 49, k, t, aS[3], aQ[3]);
    __syncthreads();
    pyr_step<7, 3>(s4, s5, g_d5 + blk * 9, k, t, aS[4], aQ[4]);
    __syncthreads();
    pyr_step<3, 1>(s5, (float*)0, g_d6 + blk, k, t, aS[5], aQ[5]);

    // block-reduce 6 stat pairs (double)
    int lane = t & 31, wid = t >> 5;
    #pragma unroll
    for (int l = 0; l < 6; ++l)
        #pragma unroll
        for (int r = 16; r; r >>= 1) {
            aS[l] += __shfl_down_sync(0xFFFFFFFFu, aS[l], r);
            aQ[l] += __shfl_down_sync(0xFFFFFFFFu, aQ[l], r);
        }
    if (lane == 0)
        #pragma unroll
        for (int l = 0; l < 6; ++l) { wS[wid][l] = aS[l]; wQ[wid][l] = aQ[l]; }
    __syncthreads();
    if (t < 6) {
        double S = 0.0, Q = 0.0;
        #pragma unroll
        for (int j = 0; j < 8; ++j) { S += wS[j][t]; Q += wQ[j][t]; }
        atomicAdd(&g_lvS[t * 32 + c], S);
        atomicAdd(&g_lvQ[t * 32 + c], Q);
    }
}

// ---------------- 6: branch coefficient finalize ----------------------------
__global__ void coef_kernel(
        const float* __restrict__ kw, const float* __restrict__ gw, const float* __restrict__ bw,
        const float* __restrict__ kh, const float* __restrict__ gh, const float* __restrict__ bh) {
    int t = threadIdx.x;
    if (t < 192) {
        int l = t >> 5, c = t & 31;
        double mean = g_lvS[t] / NPIXD;
        double var  = g_lvQ[t] / NPIXD - mean * mean;
        double k = (double)kw[c];
        double inv = 1.0 / sqrt(k * k * var + 1e-5);
        g_cA[l * 64 + c] = (float)(k * gw[c] * inv);
        g_cB[l * 64 + c] = (float)(bw[c] - k * mean * gw[c] * inv);
        k = (double)kh[c];
        inv = 1.0 / sqrt(k * k * var + 1e-5);
        g_cA[l * 64 + 32 + c] = (float)(k * gh[c] * inv);
        g_cB[l * 64 + 32 + c] = (float)(bh[c] - k * mean * gh[c] * inv);
    }
}

// ---------------- 7: final gather + sum over 6 levels (4 px/thread) ---------
__global__ __launch_bounds__(256) void final_kernel(float* __restrict__ out) {
    __shared__ float sA[384], sB[384];
    for (int i = threadIdx.x; i < 384; i += 256) { sA[i] = g_cA[i]; sB[i] = g_cB[i]; }
    __syncthreads();

    int idx = blockIdx.x * 256 + threadIdx.x;
    int x4 = (idx & 127) << 2;
    int y  = (idx >> 7) & 511;
    int ch = (idx >> 16) & 31;
    int b  = idx >> 21;
    float aw[4] = {0.f,0.f,0.f,0.f};
    float ah[4] = {0.f,0.f,0.f,0.f};

    #define LVL(L, HH, PTR) { \
        int ri = (y * HH) >> 9; \
        const float* rowp = PTR + ((b * 32 + ch) * HH + ri) * HH; \
        float A0 = sA[(L)*64+ch], B0 = sB[(L)*64+ch]; \
        float A1 = sA[(L)*64+32+ch], B1 = sB[(L)*64+32+ch]; \
        _Pragma("unroll") \
        for (int p = 0; p < 4; ++p) { \
            int ci = ((x4 + p) * HH) >> 9; \
            float dv = rowp[ci]; \
            float tw = fmaf(dv, A0, B0); aw[p] += fmaxf(tw, 0.01f * tw); \
            float th = fmaf(dv, A1, B1); ah[p] += fmaxf(th, 0.01f * th); } }

    LVL(0, 171, g_d1)
    LVL(1, 57,  g_d2)
    LVL(2, 19,  g_d3)
    LVL(3, 7,   g_d4)
    LVL(4, 3,   g_d5)
    LVL(5, 1,   g_d6)
    #undef LVL

    int ob = ((b * 64 + ch) << 18) + (y << 9) + x4;
    *(float4*)(out + ob) = make_float4(aw[0], aw[1], aw[2], aw[3]);
    *(float4*)(out + ob + (32 << 18)) = make_float4(ah[0], ah[1], ah[2], ah[3]);
}

// ---------------- launch ----------------------------------------------------
extern "C" void kernel_launch(void* const* d_in, const int* in_sizes, int n_in,
                              void* d_out, int out_size) {
    const float* x    = (const float*)d_in[0];
    const float* w1   = (const float*)d_in[1];
    const float* b1   = (const float*)d_in[2];
    const float* w2   = (const float*)d_in[3];
    const float* b2   = (const float*)d_in[4];
    const float* bn1g = (const float*)d_in[5];
    const float* bn1b = (const float*)d_in[6];
    const float* w3   = (const float*)d_in[7];
    const float* b3   = (const float*)d_in[8];
    const float* bn2g = (const float*)d_in[9];
    const float* bn2b = (const float*)d_in[10];
    const float* kd   = (const float*)d_in[11];
    const float* kw   = (const float*)d_in[12];
    const float* bwg  = (const float*)d_in[13];
    const float* bwb  = (const float*)d_in[14];
    const float* kh   = (const float*)d_in[15];
    const float* bhg  = (const float*)d_in[16];
    const float* bhb  = (const float*)d_in[17];
    float* out = (float*)d_out;

    mode_kernel<<<dim3(64, 4, 12), 128>>>(x);
    bin_kernel<<<256, 256>>>();
    params_kernel<<<1, 1024>>>(w1, b1, w2, b2, bn1g, bn1b, w3, b3, bn2g, bn2b);
    down1_kernel<<<(B_ * 171 * 171 * 4 + 255) / 256, 256>>>(kd);
    pyr_kernel<<<128, 256>>>(kd);
    coef_kernel<<<1, 192>>>(kw, bwg, bwb, kh, bhg, bhb);
    final_kernel<<<32768, 256>>>(out);
}

// round 10
// speedup vs baseline: 1.0749x; 1.0150x over previous
#include <cuda_runtime.h>
#include <math.h>

#define B_    4
#define HW_   512
#define PLANE_ 262144
#define NBIN_ 4913
#define NPIXD 1048576.0

__device__ __align__(128) unsigned char  g_kmode[12 * PLANE_];
__device__ __align__(128) unsigned short g_bin[4 * PLANE_];
__device__ unsigned int g_hist[NBIN_];              // zero-init; re-zeroed in params_kernel
__device__ __align__(128) float g_htab[NBIN_ * 32]; // pre-BN2 "tt"
__device__ float g_d1[4 * 32 * 171 * 171];
__device__ float g_d2[4 * 32 * 57 * 57];
__device__ float g_d3[4 * 32 * 19 * 19];
__device__ float g_d4[4 * 32 * 7 * 7];
__device__ float g_d5[4 * 32 * 3 * 3];
__device__ float g_d6[4 * 32];
__device__ float g_scale2[32], g_bias2[32];
__device__ double g_lvS[192], g_lvQ[192];           // per-level (6x32) weighted stats
__device__ float g_cA[384], g_cB[384];
__device__ unsigned int g_ticket;                   // pyr last-block ticket (self-resetting)

__device__ __forceinline__ float leaky(float v) { return fmaxf(v, 0.01f * v); }

template <int H>
__device__ __forceinline__ int upcnt(int i) {
    return (512 * (i + 1) + H - 1) / H - (512 * i + H - 1) / H;
}

// ---------------- 1: mode pooling ------------------------------------------
#define MROWS 8
__global__ __launch_bounds__(128) void mode_kernel(const float* __restrict__ x) {
    __shared__ unsigned int hist[138 * 5];
    const int bc = blockIdx.z, cs = blockIdx.y;
    const int y0 = blockIdx.x * MROWS;
    const int t  = threadIdx.x;
    const int colbase = cs * 128 - 5;
    const float* img = x + bc * PLANE_;

    for (int i = t; i < 138 * 5; i += 128) hist[i] = 0;
    __syncthreads();

    auto addrow = [&](int sy, int sign) {
        int r = sy; if (r < 0) r = -r; else if (r >= HW_) r = 1022 - r;
        const float* row = img + r * HW_;
        for (int xp = t; xp < 138; xp += 128) {
            int sc = colbase + xp;
            int sx = sc < 0 ? -sc : (sc >= HW_ ? 1022 - sc : sc);
            int q = __float2int_rn(row[sx] * 15.9375f);
            q = q < 0 ? 0 : (q > 16 ? 16 : q);
            unsigned int inc = 1u << ((q & 3) * 8);
            int addr = xp * 5 + (q >> 2);
            if (sign > 0) hist[addr] += inc; else hist[addr] -= inc;
        }
    };

    for (int sy = y0 - 5; sy < y0 + 5; ++sy) addrow(sy, +1);

    for (int y = y0; y < y0 + MROWS; ++y) {
        addrow(y + 5, +1);
        __syncthreads();
        {
            unsigned int s0 = 0, s1 = 0, s2 = 0, s3 = 0, s4 = 0;
            #pragma unroll
            for (int k = 0; k < 11; ++k) {
                const unsigned int* h = &hist[(t + k) * 5];
                s0 += h[0]; s1 += h[1]; s2 += h[2]; s3 += h[3]; s4 += h[4];
            }
            unsigned int best = s0 & 255u; int bl = 0;
            #define UPD(cnt, l) { unsigned int c_ = (cnt); if (c_ > best) { best = c_; bl = (l); } }
            UPD((s0 >> 8) & 255u, 1)  UPD((s0 >> 16) & 255u, 2)  UPD(s0 >> 24, 3)
            UPD(s1 & 255u, 4) UPD((s1 >> 8) & 255u, 5) UPD((s1 >> 16) & 255u, 6) UPD(s1 >> 24, 7)
            UPD(s2 & 255u, 8) UPD((s2 >> 8) & 255u, 9) UPD((s2 >> 16) & 255u, 10) UPD(s2 >> 24, 11)
            UPD(s3 & 255u, 12) UPD((s3 >> 8) & 255u, 13) UPD((s3 >> 16) & 255u, 14) UPD(s3 >> 24, 15)
            UPD(s4 & 255u, 16)
            #undef UPD
            g_kmode[bc * PLANE_ + y * HW_ + cs * 128 + t] = (unsigned char)bl;
        }
        __syncthreads();
        addrow(y - 5, -1);
    }
}

// ---------------- 2: joint-bin plane + 17^3 histogram -----------------------
__global__ __launch_bounds__(256) void bin_kernel() {
    __shared__ unsigned int sh[NBIN_];
    int t = threadIdx.x;
    for (int i = t; i < NBIN_; i += 256) sh[i] = 0;
    __syncthreads();
    int base = blockIdx.x * 4096;
    #pragma unroll 4
    for (int i = 0; i < 16; ++i) {
        int gp = base + i * 256 + t;
        int b = gp >> 18, off = gp & (PLANE_ - 1);
        const unsigned char* p = g_kmode + b * 3 * PLANE_ + off;
        int bin = p[0] + 17 * p[PLANE_] + 289 * p[2 * PLANE_];
        g_bin[gp] = (unsigned short)bin;
        atomicAdd(&sh[bin], 1u);
    }
    __syncthreads();
    for (int i = t; i < NBIN_; i += 256) {
        unsigned int v = sh[i];
        if (v) atomicAdd(&g_hist[i], v);
    }
}

// ---------------- 3: BN1 + BN2 params + htab, one block ---------------------
__global__ __launch_bounds__(1024) void params_kernel(
        const float* __restrict__ w1, const float* __restrict__ b1,
        const float* __restrict__ w2, const float* __restrict__ b2,
        const float* __restrict__ g1, const float* __restrict__ be1,
        const float* __restrict__ w3, const float* __restrict__ b3,
        const float* __restrict__ g2, const float* __restrict__ be2) {
    __shared__ float sw1[18], sb1[6], ss1[32], st1[32];
    __shared__ double rs[32][33], rq[32][33];
    int t = threadIdx.x;
    if (t < 18) sw1[t] = w1[t];
    if (t < 6)  sb1[t] = b1[t];
    __syncthreads();

    int c = t & 31, g = t >> 5;
    float w2c[6];
    #pragma unroll
    for (int o = 0; o < 6; ++o) w2c[o] = w2[c * 6 + o];
    float bc2 = b2[c];

    // pass A: BN1 stats
    double s = 0.0, q = 0.0;
    for (int bin = g; bin < NBIN_; bin += 32) {
        unsigned int cnt = g_hist[bin];
        if (!cnt) continue;
        int k2 = bin / 289, rm = bin - 289 * k2, k1 = rm / 17, k0 = rm - 17 * k1;
        float x0 = k0 * 0.0625f, x1 = k1 * 0.0625f, x2 = k2 * 0.0625f;
        float v = bc2;
        #pragma unroll
        for (int o = 0; o < 6; ++o) {
            float m = fmaf(sw1[o*3+2], x2, fmaf(sw1[o*3+1], x1, fmaf(sw1[o*3], x0, sb1[o])));
            v = fmaf(w2c[o], leaky(m), v);
        }
        double cf = (double)cnt;
        s += cf * v; q += cf * ((double)v * v);
    }
    rs[g][c] = s; rq[g][c] = q;
    __syncthreads();
    if (t < 32) {
        double S = 0.0, Q = 0.0;
        for (int j = 0; j < 32; ++j) { S += rs[j][t]; Q += rq[j][t]; }
        double mean = S / NPIXD, var = Q / NPIXD - mean * mean;
        float sc = g1[t] * (float)(1.0 / sqrt(var + 1e-5));
        ss1[t] = sc; st1[t] = be1[t] - (float)mean * sc;
    }
    __syncthreads();

    // pass B: chained BN2 stats + htab store (pre-BN2 tt)
    float s1 = ss1[c], t1 = st1[c], w3c = w3[c], b3c = b3[c];
    s = 0.0; q = 0.0;
    for (int bin = g; bin < NBIN_; bin += 32) {
        int k2 = bin / 289, rm = bin - 289 * k2, k1 = rm / 17, k0 = rm - 17 * k1;
        float x0 = k0 * 0.0625f, x1 = k1 * 0.0625f, x2 = k2 * 0.0625f;
        float v = bc2;
        #pragma unroll
        for (int o = 0; o < 6; ++o) {
            float m = fmaf(sw1[o*3+2], x2, fmaf(sw1[o*3+1], x1, fmaf(sw1[o*3], x0, sb1[o])));
            v = fmaf(w2c[o], leaky(m), v);
        }
        float u  = leaky(fmaf(v, s1, t1));
        float tt = fmaf(u, w3c, b3c);
        g_htab[bin * 32 + c] = tt;
        double cf = (double)g_hist[bin];
        s += cf * tt; q += cf * ((double)tt * tt);
    }
    __syncthreads();
    rs[g][c] = s; rq[g][c] = q;
    __syncthreads();
    if (t < 32) {
        double S = 0.0, Q = 0.0;
        for (int j = 0; j < 32; ++j) { S += rs[j][t]; Q += rq[j][t]; }
        double mean = S / NPIXD, var = Q / NPIXD - mean * mean;
        float sc = g2[t] * (float)(1.0 / sqrt(var + 1e-5));
        g_scale2[t] = sc; g_bias2[t] = be2[t] - (float)mean * sc;
    }
    // cleanup for graph replay + zero level accumulators (all 6 levels)
    for (int i = t; i < NBIN_; i += 1024) g_hist[i] = 0u;
    if (t < 192) { g_lvS[t] = 0.0; g_lvQ[t] = 0.0; }
}

// ---------------- 4: level-1 downsample (pure compute, no stats) ------------
__global__ __launch_bounds__(256) void down1_kernel(const float* __restrict__ kd) {
    __shared__ float skd[288];
    int t = threadIdx.x;
    for (int i = t; i < 288; i += 256) skd[i] = kd[i];
    __syncthreads();

    int gid = blockIdx.x * 256 + t;
    const int TOT = B_ * 171 * 171 * 4;
    if (gid >= TOT) return;
    int cg = gid & 3; int rest = gid >> 2;
    int xo = rest % 171; int r2 = rest / 171;
    int yo = r2 % 171;   int b  = r2 / 171;
    int c0 = cg * 8;

    float s2[8], t2[8];
    #pragma unroll
    for (int j = 0; j < 8; ++j) { s2[j] = g_scale2[c0 + j]; t2[j] = g_bias2[c0 + j]; }

    const unsigned short* binp = g_bin + b * PLANE_;
    float acc[8] = {0.f,0.f,0.f,0.f,0.f,0.f,0.f,0.f};
    #pragma unroll
    for (int r = 0; r < 3; ++r) {
        int iy = 3 * yo - 1 + r;
        if (iy < 0 || iy >= HW_) continue;
        #pragma unroll
        for (int sx = 0; sx < 3; ++sx) {
            int ix = 3 * xo - 1 + sx;
            if (ix < 0 || ix >= HW_) continue;
            int bin = binp[iy * HW_ + ix];
            const float4* hrow = (const float4*)(g_htab + bin * 32 + c0);
            float4 v0 = hrow[0], v1 = hrow[1];
            float hv[8] = {v0.x,v0.y,v0.z,v0.w,v1.x,v1.y,v1.z,v1.w};
            int kb = r * 3 + sx;
            #pragma unroll
            for (int j = 0; j < 8; ++j) {
                float h = leaky(fmaf(hv[j], s2[j], t2[j]));
                acc[j] = fmaf(skd[(c0 + j) * 9 + kb], h, acc[j]);
            }
        }
    }
    float* outp = g_d1 + ((b * 32 + c0) * 171 + yo) * 171 + xo;
    #pragma unroll
    for (int j = 0; j < 8; ++j) outp[j * 29241] = acc[j];
}

// ---------------- 5: per-plane pyramid + stats lvl0..5 + coef (last block) --
template <int HIN, int HOUT>
__device__ __forceinline__ void pyr_step(const float* __restrict__ in,
                                         float* sh_out, float* __restrict__ g_out,
                                         const float* k, int t,
                                         double& aS, double& aQ) {
    const int N = HOUT * HOUT;
    for (int idx = t; idx < N; idx += 256) {
        int yo = idx / HOUT, xo = idx - yo * HOUT;
        float acc = 0.f;
        #pragma unroll
        for (int r = 0; r < 3; ++r) {
            int iy = 3 * yo - 1 + r;
            if (iy < 0 || iy >= HIN) continue;
            #pragma unroll
            for (int sx = 0; sx < 3; ++sx) {
                int ix = 3 * xo - 1 + sx;
                if (ix < 0 || ix >= HIN) continue;
                acc = fmaf(k[r * 3 + sx], in[iy * HIN + ix], acc);
            }
        }
        if (sh_out) sh_out[idx] = acc;
        g_out[idx] = acc;
        double w = (double)(upcnt<HOUT>(yo) * upcnt<HOUT>(xo));
        double a = (double)acc;
        aS += w * a; aQ += w * a * a;
    }
}

__global__ __launch_bounds__(256) void pyr_kernel(const float* __restrict__ kd,
        const float* __restrict__ kw, const float* __restrict__ gw, const float* __restrict__ bw,
        const float* __restrict__ kh, const float* __restrict__ gh, const float* __restrict__ bh) {
    __shared__ float s2[57 * 57];
    __shared__ float s3[19 * 19];
    __shared__ float s4[49];
    __shared__ float s5[9];
    __shared__ double wS[8][6], wQ[8][6];
    __shared__ int slast;
    int t = threadIdx.x;
    int blk = blockIdx.x;            // b*32 + c
    int c = blk & 31;
    float k[9];
    #pragma unroll
    for (int j = 0; j < 9; ++j) k[j] = kd[c * 9 + j];

    double aS[6] = {0,0,0,0,0,0}, aQ[6] = {0,0,0,0,0,0};

    // level-0 stats over the d1 plane (hot in L2; 2 doubles/thread only)
    {
        const float* d1p = g_d1 + blk * 29241;
        for (int idx = t; idx < 29241; idx += 256) {
            int yo = idx / 171, xo = idx - yo * 171;
            double w = (double)(upcnt<171>(yo) * upcnt<171>(xo));
            double a = (double)d1p[idx];
            aS[0] += w * a; aQ[0] += w * a * a;
        }
    }

    pyr_step<171, 57>(g_d1 + blk * 29241, s2, g_d2 + blk * 3249, k, t, aS[1], aQ[1]);
    __syncthreads();
    pyr_step<57, 19>(s2, s3, g_d3 + blk * 361, k, t, aS[2], aQ[2]);
    __syncthreads();
    pyr_step<19, 7>(s3, s4, g_d4 + blk * 49, k, t, aS[3], aQ[3]);
    __syncthreads();
    pyr_step<7, 3>(s4, s5, g_d5 + blk * 9, k, t, aS[4], aQ[4]);
    __syncthreads();
    pyr_step<3, 1>(s5, (float*)0, g_d6 + blk, k, t, aS[5], aQ[5]);

    // block-reduce 6 stat pairs (double)
    int lane = t & 31, wid = t >> 5;
    #pragma unroll
    for (int l = 0; l < 6; ++l)
        #pragma unroll
        for (int r = 16; r; r >>= 1) {
            aS[l] += __shfl_down_sync(0xFFFFFFFFu, aS[l], r);
            aQ[l] += __shfl_down_sync(0xFFFFFFFFu, aQ[l], r);
        }
    if (lane == 0)
        #pragma unroll
        for (int l = 0; l < 6; ++l) { wS[wid][l] = aS[l]; wQ[wid][l] = aQ[l]; }
    __syncthreads();
    if (t < 6) {
        double S = 0.0, Q = 0.0;
        #pragma unroll
        for (int j = 0; j < 8; ++j) { S += wS[j][t]; Q += wQ[j][t]; }
        atomicAdd(&g_lvS[t * 32 + c], S);
        atomicAdd(&g_lvQ[t * 32 + c], Q);
    }

    // last-block ticket: finalize branch coefficients inline
    __threadfence();
    __syncthreads();
    if (t == 0) {
        unsigned int old = atomicAdd(&g_ticket, 1u);
        slast = (old == 127u);
    }
    __syncthreads();
    if (slast) {
        if (t < 192) {
            int l = t >> 5, cc = t & 31;
            double mean = g_lvS[t] / NPIXD;
            double var  = g_lvQ[t] / NPIXD - mean * mean;
            double kk = (double)kw[cc];
            double inv = 1.0 / sqrt(kk * kk * var + 1e-5);
            g_cA[l * 64 + cc] = (float)(kk * gw[cc] * inv);
            g_cB[l * 64 + cc] = (float)(bw[cc] - kk * mean * gw[cc] * inv);
            kk = (double)kh[cc];
            inv = 1.0 / sqrt(kk * kk * var + 1e-5);
            g_cA[l * 64 + 32 + cc] = (float)(kk * gh[cc] * inv);
            g_cB[l * 64 + 32 + cc] = (float)(bh[cc] - kk * mean * gh[cc] * inv);
        }
        if (t == 0) g_ticket = 0u;   // reset for next graph replay
        __threadfence();
    }
}

// ---------------- 6: final gather + sum, shared-staged rows -----------------
// Block = (b,ch) fixed, 2 consecutive y rows, full x range (4 px/thread).
// Stage the six full coarse rows (258 floats) per y into shared.
__global__ __launch_bounds__(256) void final_kernel(float* __restrict__ out) {
    __shared__ float srow[2][264];
    __shared__ float sAB[4][6];      // [Aw,Bw,Ah,Bh][level] for this channel
    int t = threadIdx.x;
    int base = blockIdx.x * 256;
    int y0 = (base >> 7) & 511;      // even; block covers y0, y0+1
    int ch = (base >> 16) & 31;
    int b  = base >> 21;

    if (t < 24) {
        int l = t & 7;
        if (l < 6) {
            int kind = t >> 3;       // 0:Aw 1:Bw 2:Ah
            if (kind == 0) sAB[0][l] = g_cA[l * 64 + ch];
            else if (kind == 1) sAB[1][l] = g_cB[l * 64 + ch];
            else sAB[2][l] = g_cA[l * 64 + 32 + ch];
        }
    } else if (t >= 32 && t < 40) {
        int l = t - 32;
        if (l < 6) sAB[3][l] = g_cB[l * 64 + 32 + ch];
    }

    // stage rows: offsets {0,171,228,247,254,257} lengths {171,57,19,7,3,1}
    const int pc = b * 32 + ch;
    for (int j = t; j < 516; j += 256) {
        int row = j >= 258 ? 1 : 0;
        int off = j - row * 258;
        int y = y0 + row;
        float v;
        if (off < 171)      v = g_d1[(pc * 171 + ((y * 171) >> 9)) * 171 + off];
        else if (off < 228) v = g_d2[(pc * 57  + ((y * 57)  >> 9)) * 57  + (off - 171)];
        else if (off < 247) v = g_d3[(pc * 19  + ((y * 19)  >> 9)) * 19  + (off - 228)];
        else if (off < 254) v = g_d4[(pc * 7   + ((y * 7)   >> 9)) * 7   + (off - 247)];
        else if (off < 257) v = g_d5[(pc * 3   + ((y * 3)   >> 9)) * 3   + (off - 254)];
        else                v = g_d6[pc];
        srow[row][off] = v;
    }
    __syncthreads();

    int yrow = t >> 7;               // 0 or 1
    int x4 = (t & 127) << 2;
    const float* sr = srow[yrow];
    float aw[4] = {0.f,0.f,0.f,0.f};
    float ah[4] = {0.f,0.f,0.f,0.f};

    #define LVL(L, HH, OFF) { \
        float A0 = sAB[0][L], B0 = sAB[1][L], A1 = sAB[2][L], B1 = sAB[3][L]; \
        _Pragma("unroll") \
        for (int p = 0; p < 4; ++p) { \
            float dv = sr[OFF + (((x4 + p) * HH) >> 9)]; \
            float tw = fmaf(dv, A0, B0); aw[p] += fmaxf(tw, 0.01f * tw); \
            float th = fmaf(dv, A1, B1); ah[p] += fmaxf(th, 0.01f * th); } }

    LVL(0, 171, 0)
    LVL(1, 57,  171)
    LVL(2, 19,  228)
    LVL(3, 7,   247)
    LVL(4, 3,   254)
    LVL(5, 1,   257)
    #undef LVL

    int y = y0 + yrow;
    int ob = ((b * 64 + ch) << 18) + (y << 9) + x4;
    __stcs((float4*)(out + ob), make_float4(aw[0], aw[1], aw[2], aw[3]));
    __stcs((float4*)(out + ob + (32 << 18)), make_float4(ah[0], ah[1], ah[2], ah[3]));
}

// ---------------- launch ----------------------------------------------------
extern "C" void kernel_launch(void* const* d_in, const int* in_sizes, int n_in,
                              void* d_out, int out_size) {
    const float* x    = (const float*)d_in[0];
    const float* w1   = (const float*)d_in[1];
    const float* b1   = (const float*)d_in[2];
    const float* w2   = (const float*)d_in[3];
    const float* b2   = (const float*)d_in[4];
    const float* bn1g = (const float*)d_in[5];
    const float* bn1b = (const float*)d_in[6];
    const float* w3   = (const float*)d_in[7];
    const float* b3   = (const float*)d_in[8];
    const float* bn2g = (const float*)d_in[9];
    const float* bn2b = (const float*)d_in[10];
    const float* kd   = (const float*)d_in[11];
    const float* kw   = (const float*)d_in[12];
    const float* bwg  = (const float*)d_in[13];
    const float* bwb  = (const float*)d_in[14];
    const float* kh   = (const float*)d_in[15];
    const float* bhg  = (const float*)d_in[16];
    const float* bhb  = (const float*)d_in[17];
    float* out = (float*)d_out;

    mode_kernel<<<dim3(64, 4, 12), 128>>>(x);
    bin_kernel<<<256, 256>>>();
    params_kernel<<<1, 1024>>>(w1, b1, w2, b2, bn1g, bn1b, w3, b3, bn2g, bn2b);
    down1_kernel<<<(B_ * 171 * 171 * 4 + 255) / 256, 256>>>(kd);
    pyr_kernel<<<128, 256>>>(kd, kw, bwg, bwb, kh, bhg, bhb);
    final_kernel<<<32768, 256>>>(out);
}